// round 16
// baseline (speedup 1.0000x reference)
#include <cuda_runtime.h>
#include <cuda_fp16.h>
#include <cstdint>

// MX (block-32, E8M0 scale, E4M3 elements) quantize-dequantize using the
// HARDWARE E4M3 converter (cvt.rn.satfinite.e4m3x2.f32 = RNE, sat at 448,
// E4M3 subnormals — exactly the reference semantics). Scales are exact
// powers of two from the block-amax exponent byte.
//
// PERSISTENT grid-stride form: grid = 148 SMs x 8 CTAs = 1184 resident CTAs,
// each looping over tiles — removes the ~7 wave transitions (+ launch/drain
// memory-idle ramps) of the 8192-CTA one-shot grid.
//
// Layout per tile: 256 threads x VPT=2 segments of 8 contiguous floats.
// Warp covers 256 contiguous floats = 8 MX blocks; block = 4 adjacent lanes
// -> reduction is 2 x (shfl_xor + vmaxu4) on packed exponent bytes.
// Streaming hints (.cs) both ways — best measured harness config.

#define VPT 2
#define TPB 256
#define SEGS_PER_TILE (TPB * VPT)

__device__ __forceinline__ float2 qdq2(float a, float b, float inv_scale, float scale) {
    float sa = a * inv_scale;                // exact power-of-two multiply
    float sb = b * inv_scale;
    unsigned short q;
    asm("cvt.rn.satfinite.e4m3x2.f32 %0, %1, %2;" : "=h"(q) : "f"(sb), "f"(sa));
    unsigned hh;
    asm("cvt.rn.f16x2.e4m3x2 %0, %1;" : "=r"(hh) : "h"(q));
    __half2 h2 = *reinterpret_cast<__half2*>(&hh);
    float2 f = __half22float2(h2);           // exact widen
    f.x *= scale;                            // exact power-of-two multiply
    f.y *= scale;
    return f;
}

template <bool EXACT>
__global__ void __launch_bounds__(TPB) mx_qdq_kernel(const float* __restrict__ in,
                                                     float* __restrict__ out,
                                                     int n8, int n_tiles) {
    for (int tile = blockIdx.x; tile < n_tiles; tile += gridDim.x) {
        int base = tile * SEGS_PER_TILE + threadIdx.x;   // segment index (8 floats)

        // ---- front-batched streaming loads (4 x LDG.128) ----
        float4 v[VPT][2];
#pragma unroll
        for (int j = 0; j < VPT; j++) {
            int seg = base + j * TPB;
            if (EXACT || seg < n8) {
                const float4* src = (const float4*)(in + (size_t)seg * 8);
                v[j][0] = __ldcs(src);
                v[j][1] = __ldcs(src + 1);
            }
        }

        // ---- per-segment abs-bit max -> exponent byte, packed per-u32 ----
        unsigned p = 0u;
#pragma unroll
        for (int j = 0; j < VPT; j++) {
            unsigned a = 0u;
#pragma unroll
            for (int h = 0; h < 2; h++) {
                a = max(a, __float_as_uint(v[j][h].x) & 0x7FFFFFFFu);
                a = max(a, __float_as_uint(v[j][h].y) & 0x7FFFFFFFu);
                a = max(a, __float_as_uint(v[j][h].z) & 0x7FFFFFFFu);
                a = max(a, __float_as_uint(v[j][h].w) & 0x7FFFFFFFu);
            }
            if (!EXACT && (base + j * TPB) >= n8) a = 0u;
            p |= (a >> 23) << (8 * j);
        }

        // ---- 4-lane group reduction, byte-wise max (block = 4 adjacent lanes) ----
        p = __vmaxu4(p, __shfl_xor_sync(0xFFFFFFFFu, p, 1));
        p = __vmaxu4(p, __shfl_xor_sync(0xFFFFFFFFu, p, 2));

        // ---- HW-cvt quantize-dequantize + streaming store ----
#pragma unroll
        for (int j = 0; j < VPT; j++) {
            int seg = base + j * TPB;
            if (!EXACT && seg >= n8) continue;

            // se = clip(floor(log2(amax)) - 8, -127, 127); low clip via max(E,8).
            // Subnormal/zero amax -> se=-127 (all-zero block outputs zeros anyway).
            unsigned mE = max((p >> (8 * j)) & 0xFFu, 8u);
            float inv_scale = __uint_as_float((262u - mE) << 23);        // 2^-se (normal)
            float scale = (mE > 8u) ? __uint_as_float((mE - 8u) << 23)   // 2^se
                                    : __uint_as_float(0x00400000u);      // 2^-127 (subnormal)

            float4* dst = (float4*)(out + (size_t)seg * 8);
#pragma unroll
            for (int h = 0; h < 2; h++) {
                float2 lo = qdq2(v[j][h].x, v[j][h].y, inv_scale, scale);
                float2 hi = qdq2(v[j][h].z, v[j][h].w, inv_scale, scale);
                float4 o; o.x = lo.x; o.y = lo.y; o.z = hi.x; o.w = hi.y;
                __stcs(dst + h, o);
            }
        }
    }
}

extern "C" void kernel_launch(void* const* d_in, const int* in_sizes, int n_in,
                              void* d_out, int out_size) {
    const float* x = (const float*)d_in[0];
    float* out = (float*)d_out;
    int n = in_sizes[0];            // 4096*8192
    int n8 = n / 8;                 // 32B segments
    int n_tiles = (n8 + SEGS_PER_TILE - 1) / SEGS_PER_TILE;
    int grid = 148 * 8;             // persistent: 8 CTAs/SM x 148 SMs
    if (grid > n_tiles) grid = n_tiles;
    if (n8 % SEGS_PER_TILE == 0) {
        mx_qdq_kernel<true><<<grid, TPB>>>(x, out, n8, n_tiles);
    } else {
        mx_qdq_kernel<false><<<grid, TPB>>>(x, out, n8, n_tiles);
    }
}